// round 6
// baseline (speedup 1.0000x reference)
#include <cuda_runtime.h>

// PoseODE: y' = MLP(y), y0 = 0, batch-invariant -> single 768-vector trajectory.
// 512 sequential matvec stages. Cross-CTA exchange: each warp's lane0 publishes
// its column as a tagged 8B slot (single-copy atomic); 128 poller threads each
// watch one CTA's 6 slots. One __syncthreads per round. Monotonic tags ->
// no init, no barriers, replay-safe.

#define F      768
#define G      128   // CTAs
#define T      192   // 6 warps; warp w owns column blockIdx.x*6 + w
#define NSTEP  64

// slot = {float bits, tag}; [parity][cta][slot 0..5 used, padded to 64B]
__device__ uint2 g_x[2][G][8] = {};
__device__ uint2 g_s[2][256]  = {};   // regressor rounds

static __device__ __forceinline__ uint4 ldcg_v4(const void* p) {
    uint4 r;
    asm volatile("ld.global.cg.v4.u32 {%0,%1,%2,%3},[%4];"
                 : "=r"(r.x), "=r"(r.y), "=r"(r.z), "=r"(r.w) : "l"(p));
    return r;
}
static __device__ __forceinline__ void pub8(uint2* s, float v, unsigned tag) {
    asm volatile("st.global.cg.v2.u32 [%0],{%1,%2};"
                 :: "l"(s), "r"(__float_as_uint(v)), "r"(tag) : "memory");
}
static __device__ __forceinline__ float wait8(const uint2* s, unsigned tag) {
    unsigned v, t;
    do {
        asm volatile("ld.global.cg.v2.u32 {%0,%1},[%2];" : "=r"(v), "=r"(t) : "l"(s));
    } while (t != tag);
    return __uint_as_float(v);
}

// Poll one CTA's 6 slots (48B) until all tags match; return the 6 values.
static __device__ __forceinline__ void wait_packet(const uint2* p, unsigned tag, float* out) {
    uint4 a, b, c;
    do {
        a = ldcg_v4(p);
        b = ldcg_v4(p + 2);
        c = ldcg_v4(p + 4);
    } while ((a.y ^ tag) | (a.w ^ tag) | (b.y ^ tag) |
             (b.w ^ tag) | (c.y ^ tag) | (c.w ^ tag));
    out[0] = __uint_as_float(a.x); out[1] = __uint_as_float(a.z);
    out[2] = __uint_as_float(b.x); out[3] = __uint_as_float(b.z);
    out[4] = __uint_as_float(c.x); out[5] = __uint_as_float(c.z);
}

static __device__ __forceinline__ float lrelu(float x) { return x > 0.0f ? x : 0.1f * x; }

static __device__ __forceinline__ float warp_sum(float a) {
#pragma unroll
    for (int o = 16; o; o >>= 1) a += __shfl_xor_sync(0xffffffffu, a, o);
    return a;
}

// Block-wide dot of SMEM vector src[0..L) with column `col` of wmat[L][outF].
__device__ __forceinline__ float block_dot(const float* src, int L,
                                           const float* wmat, int outF, int col,
                                           const float* bias, volatile float* red) {
    int tid = threadIdx.x, warp = tid >> 5, lane = tid & 31;
    float p = 0.0f;
    for (int i = tid; i < L; i += T) p = fmaf(src[i], __ldg(&wmat[i * outF + col]), p);
    p = warp_sum(p);
    if (lane == 0) red[warp] = p;
    __syncthreads();
    float s = 0.0f;
    if (tid == 0) {
        for (int w = 0; w < 6; w++) s += red[w];
        s += __ldg(&bias[col]);
    }
    __syncthreads();
    return s;
}

__global__ __launch_bounds__(T, 1) void pose_ode_kernel(
    const float* __restrict__ ts,
    const float* __restrict__ w1, const float* __restrict__ b1,
    const float* __restrict__ w2, const float* __restrict__ b2,
    const float* __restrict__ rw1, const float* __restrict__ rb1,
    const float* __restrict__ rw2, const float* __restrict__ rb2,
    const float* __restrict__ rw3, const float* __restrict__ rb3,
    const float* __restrict__ rw4, const float* __restrict__ rb4,
    float* __restrict__ out, int out_n)
{
    __shared__ float4 vsm4[F / 4];       // stage input vector / final yT
    __shared__ float4 hsm4[F / 4];       // hidden vector / regressor scratch
    __shared__ float  wstage[6 * F];     // 18 KB one-time weight staging
    __shared__ float  red[8];
    __shared__ float  pose_s[8];
    __shared__ float  dts[NSTEP];

    float* vsm = (float*)vsm4;
    float* hsm = (float*)hsm4;

    const int tid  = threadIdx.x;
    const int warp = tid >> 5;
    const int lane = tid & 31;
    const int bid  = blockIdx.x;
    const int c0   = bid * 6;
    const int j    = c0 + warp;          // this warp's output column

    if (tid < NSTEP) dts[tid] = __ldg(&ts[tid + 1]) - __ldg(&ts[tid]);

    // ---- stage weight columns into SMEM (coalesced), then into registers ----
    float4 w1r[6], w2r[6];
    for (int idx = tid; idx < 6 * F; idx += T) {
        int i = idx / 6, r = idx - i * 6;
        wstage[r * F + i] = w1[i * F + c0 + r];
    }
    __syncthreads();
#pragma unroll
    for (int k = 0; k < 6; k++)
        w1r[k] = ((const float4*)(wstage + warp * F))[k * 32 + lane];
    __syncthreads();
    for (int idx = tid; idx < 6 * F; idx += T) {
        int i = idx / 6, r = idx - i * 6;
        wstage[r * F + i] = w2[i * F + c0 + r];
    }
    __syncthreads();
#pragma unroll
    for (int k = 0; k < 6; k++)
        w2r[k] = ((const float4*)(wstage + warp * F))[k * 32 + lane];

    const float b1c = __ldg(&b1[j]);
    const float b2c = __ldg(&b2[j]);

    // ---- initial state: y0 = 0 ----
    vsm4[tid] = make_float4(0.f, 0.f, 0.f, 0.f);    // T == F/4
    __syncthreads();

    // Poller thread t (<128) owns state elements [6t, 6t+6) == its packet.
    float yr[6]  = {0.f, 0.f, 0.f, 0.f, 0.f, 0.f};
    float ynr[6], k1r[6], k2r[6];
    unsigned rnd = 0;

#pragma unroll 1
    for (int s = 0; s < NSTEP; s++) {
        const float dt  = dts[s];
        const float dt3 = dt * (1.0f / 3.0f);

#pragma unroll 1
        for (int e = 0; e < 4; e++) {
            // ---- layer 1: h_j = tanh(v @ W1[:,j] + b1_j) ----
            float acc = 0.0f;
#pragma unroll
            for (int k = 0; k < 6; k++) {
                float4 a = vsm4[k * 32 + lane];
                acc = fmaf(a.x, w1r[k].x, acc);
                acc = fmaf(a.y, w1r[k].y, acc);
                acc = fmaf(a.z, w1r[k].z, acc);
                acc = fmaf(a.w, w1r[k].w, acc);
            }
            acc = warp_sum(acc);
            unsigned th = ++rnd;
            if (lane == 0) pub8(&g_x[th & 1][bid][warp], tanhf(acc + b1c), th);
            if (tid < G) {
                float hv[6];
                wait_packet(g_x[th & 1][tid], th, hv);
                float* d = hsm + tid * 6;
#pragma unroll
                for (int q = 0; q < 6; q++) d[q] = hv[q];
            }
            __syncthreads();

            // ---- layer 2: k_j = h @ W2[:,j] + b2_j ----
            float acc2 = 0.0f;
#pragma unroll
            for (int k = 0; k < 6; k++) {
                float4 a = hsm4[k * 32 + lane];
                acc2 = fmaf(a.x, w2r[k].x, acc2);
                acc2 = fmaf(a.y, w2r[k].y, acc2);
                acc2 = fmaf(a.z, w2r[k].z, acc2);
                acc2 = fmaf(a.w, w2r[k].w, acc2);
            }
            acc2 = warp_sum(acc2);
            unsigned tk = ++rnd;
            if (lane == 0) pub8(&g_x[tk & 1][bid][warp], acc2 + b2c, tk);
            if (tid < G) {
                float kv[6];
                wait_packet(g_x[tk & 1][tid], tk, kv);
                float* v = vsm + tid * 6;
                if (e == 0) {
#pragma unroll
                    for (int q = 0; q < 6; q++) {
                        k1r[q] = kv[q];
                        ynr[q] = fmaf(dt * 0.125f, kv[q], yr[q]);
                        v[q]   = fmaf(dt3, kv[q], yr[q]);
                    }
                } else if (e == 1) {
#pragma unroll
                    for (int q = 0; q < 6; q++) {
                        k2r[q] = kv[q];
                        ynr[q] = fmaf(dt * 0.375f, kv[q], ynr[q]);
                        v[q]   = yr[q] + dt * kv[q] - dt3 * k1r[q];
                    }
                } else if (e == 2) {
#pragma unroll
                    for (int q = 0; q < 6; q++) {
                        ynr[q] = fmaf(dt * 0.375f, kv[q], ynr[q]);
                        v[q]   = yr[q] + dt * (k1r[q] - k2r[q] + kv[q]);
                    }
                } else {
#pragma unroll
                    for (int q = 0; q < 6; q++) {
                        yr[q] = fmaf(dt * 0.125f, kv[q], ynr[q]);
                        v[q]  = yr[q];
                    }
                }
            }
            __syncthreads();
        }
    }
    // vsm now holds yT (not modified below).

    // ---- regressor 768->128->256->128->6 via tagged 8B rounds ----
    {
        float o1 = block_dot(vsm, 768, rw1, 128, bid, rb1, red);
        unsigned tr = ++rnd; uint2* b = g_s[tr & 1];
        if (tid == 0) pub8(&b[bid], lrelu(o1), tr);
        if (tid < 128) hsm[tid] = wait8(&b[tid], tr);
        __syncthreads();

        float o2a = block_dot(hsm, 128, rw2, 256, bid,       rb2, red);
        float o2b = block_dot(hsm, 128, rw2, 256, bid + 128, rb2, red);
        tr = ++rnd; b = g_s[tr & 1];
        if (tid == 0) {
            pub8(&b[bid],       lrelu(o2a), tr);
            pub8(&b[bid + 128], lrelu(o2b), tr);
        }
        for (int i = tid; i < 256; i += T) hsm[i] = wait8(&b[i], tr);
        __syncthreads();

        float o3 = block_dot(hsm, 256, rw3, 128, bid, rb3, red);
        tr = ++rnd; b = g_s[tr & 1];
        if (tid == 0) pub8(&b[bid], lrelu(o3), tr);
        __syncthreads();                     // hsm reads done; safe to overwrite
        if (tid < 128) hsm[tid] = wait8(&b[tid], tr);
        __syncthreads();

        float o4 = block_dot(hsm, 128, rw4, 6, bid % 6, rb4, red);
        tr = ++rnd; b = g_s[tr & 1];
        if (tid == 0 && bid < 6) pub8(&b[bid], o4, tr);   // no activation
        if (tid < 6) pose_s[tid] = wait8(&b[tid], tr);
        __syncthreads();
    }

    // ---- outputs: [pose (256*6) | yT (256*768)] ----
    for (int idx = bid * T + tid; idx < out_n; idx += G * T) {
        out[idx] = (idx < 1536) ? pose_s[idx % 6] : vsm[(idx - 1536) % 768];
    }
}

extern "C" void kernel_launch(void* const* d_in, const int* in_sizes, int n_in,
                              void* d_out, int out_size) {
    // order: fv, fv_alter, fi, dec (unused), ts, ode_w1, ode_b1, ode_w2, ode_b2,
    // reg_w1, reg_b1, reg_w2, reg_b2, reg_w3, reg_b3, reg_w4, reg_b4
    const float* ts  = (const float*)d_in[4];
    const float* w1  = (const float*)d_in[5];
    const float* b1  = (const float*)d_in[6];
    const float* w2  = (const float*)d_in[7];
    const float* b2  = (const float*)d_in[8];
    const float* rw1 = (const float*)d_in[9];
    const float* rb1 = (const float*)d_in[10];
    const float* rw2 = (const float*)d_in[11];
    const float* rb2 = (const float*)d_in[12];
    const float* rw3 = (const float*)d_in[13];
    const float* rb3 = (const float*)d_in[14];
    const float* rw4 = (const float*)d_in[15];
    const float* rb4 = (const float*)d_in[16];

    pose_ode_kernel<<<G, T>>>(ts, w1, b1, w2, b2,
                              rw1, rb1, rw2, rb2, rw3, rb3, rw4, rb4,
                              (float*)d_out, out_size);
}

// round 7
// speedup vs baseline: 1.5241x; 1.5241x over previous
#include <cuda_runtime.h>

// PoseODE: y' = MLP(y), y0 = 0, batch-invariant -> single 768-vector trajectory.
// 512 sequential matvec stages. Cross-CTA exchange: each warp's lane0 publishes
// its column as a tagged 8B slot (single-copy atomic). CRITICAL ordering: a
// __syncthreads separates publish from poll, so no warp spins (hogging LSU)
// while sibling warps still need to compute+publish. Monotonic tags ->
// no init, no grid barrier, replay-safe (stale tags match only with identical
// deterministic values).

#define F      768
#define G      128   // CTAs
#define T      192   // 6 warps; warp w owns column blockIdx.x*6 + w
#define NSTEP  64

// slot = {float bits, tag}; [parity][cta][slot 0..5 used, 8 slots = 64B row]
__device__ __align__(128) uint2 g_x[2][G][8] = {};
__device__ __align__(128) uint2 g_s[2][256]  = {};   // regressor rounds

static __device__ __forceinline__ uint4 ldcg_v4(const void* p) {
    uint4 r;
    asm volatile("ld.global.cg.v4.u32 {%0,%1,%2,%3},[%4];"
                 : "=r"(r.x), "=r"(r.y), "=r"(r.z), "=r"(r.w) : "l"(p));
    return r;
}
static __device__ __forceinline__ void pub8(uint2* s, float v, unsigned tag) {
    asm volatile("st.global.cg.v2.u32 [%0],{%1,%2};"
                 :: "l"(s), "r"(__float_as_uint(v)), "r"(tag) : "memory");
}
static __device__ __forceinline__ float wait8(const uint2* s, unsigned tag) {
    unsigned v, t;
    do {
        asm volatile("ld.global.cg.v2.u32 {%0,%1},[%2];" : "=r"(v), "=r"(t) : "l"(s));
    } while (t != tag);
    return __uint_as_float(v);
}

// Poll one CTA's 6 slots (48B of one 64B line) until all tags match.
static __device__ __forceinline__ void wait_packet(const uint2* p, unsigned tag, float* out) {
    uint4 a, b, c;
    do {
        a = ldcg_v4(p);
        b = ldcg_v4(p + 2);
        c = ldcg_v4(p + 4);
    } while ((a.y ^ tag) | (a.w ^ tag) | (b.y ^ tag) |
             (b.w ^ tag) | (c.y ^ tag) | (c.w ^ tag));
    out[0] = __uint_as_float(a.x); out[1] = __uint_as_float(a.z);
    out[2] = __uint_as_float(b.x); out[3] = __uint_as_float(b.z);
    out[4] = __uint_as_float(c.x); out[5] = __uint_as_float(c.z);
}

static __device__ __forceinline__ float lrelu(float x) { return x > 0.0f ? x : 0.1f * x; }

static __device__ __forceinline__ float warp_sum(float a) {
#pragma unroll
    for (int o = 16; o; o >>= 1) a += __shfl_xor_sync(0xffffffffu, a, o);
    return a;
}

// Block-wide dot of SMEM vector src[0..L) with column `col` of wmat[L][outF].
__device__ __forceinline__ float block_dot(const float* src, int L,
                                           const float* wmat, int outF, int col,
                                           const float* bias, volatile float* red) {
    int tid = threadIdx.x, warp = tid >> 5, lane = tid & 31;
    float p = 0.0f;
    for (int i = tid; i < L; i += T) p = fmaf(src[i], __ldg(&wmat[i * outF + col]), p);
    p = warp_sum(p);
    if (lane == 0) red[warp] = p;
    __syncthreads();
    float s = 0.0f;
    if (tid == 0) {
        for (int w = 0; w < 6; w++) s += red[w];
        s += __ldg(&bias[col]);
    }
    __syncthreads();
    return s;
}

__global__ __launch_bounds__(T, 1) void pose_ode_kernel(
    const float* __restrict__ ts,
    const float* __restrict__ w1, const float* __restrict__ b1,
    const float* __restrict__ w2, const float* __restrict__ b2,
    const float* __restrict__ rw1, const float* __restrict__ rb1,
    const float* __restrict__ rw2, const float* __restrict__ rb2,
    const float* __restrict__ rw3, const float* __restrict__ rb3,
    const float* __restrict__ rw4, const float* __restrict__ rb4,
    float* __restrict__ out, int out_n)
{
    __shared__ float4 vsm4[F / 4];       // stage input vector / final yT
    __shared__ float4 hsm4[F / 4];       // hidden vector / regressor scratch
    __shared__ float  wstage[6 * F];     // 18 KB one-time weight staging
    __shared__ float  red[8];
    __shared__ float  pose_s[8];
    __shared__ float  dts[NSTEP];

    float* vsm = (float*)vsm4;
    float* hsm = (float*)hsm4;

    const int tid  = threadIdx.x;
    const int warp = tid >> 5;
    const int lane = tid & 31;
    const int bid  = blockIdx.x;
    const int c0   = bid * 6;
    const int j    = c0 + warp;          // this warp's output column

    if (tid < NSTEP) dts[tid] = __ldg(&ts[tid + 1]) - __ldg(&ts[tid]);

    // ---- stage weight columns into SMEM (coalesced), then into registers ----
    float4 w1r[6], w2r[6];
    for (int idx = tid; idx < 6 * F; idx += T) {
        int i = idx / 6, r = idx - i * 6;
        wstage[r * F + i] = w1[i * F + c0 + r];
    }
    __syncthreads();
#pragma unroll
    for (int k = 0; k < 6; k++)
        w1r[k] = ((const float4*)(wstage + warp * F))[k * 32 + lane];
    __syncthreads();
    for (int idx = tid; idx < 6 * F; idx += T) {
        int i = idx / 6, r = idx - i * 6;
        wstage[r * F + i] = w2[i * F + c0 + r];
    }
    __syncthreads();
#pragma unroll
    for (int k = 0; k < 6; k++)
        w2r[k] = ((const float4*)(wstage + warp * F))[k * 32 + lane];

    const float b1c = __ldg(&b1[j]);
    const float b2c = __ldg(&b2[j]);

    // ---- initial state: y0 = 0 ----
    vsm4[tid] = make_float4(0.f, 0.f, 0.f, 0.f);    // T == F/4
    __syncthreads();

    // Poller thread t (<128) owns state elements [6t, 6t+6) == its packet.
    float yr[6]  = {0.f, 0.f, 0.f, 0.f, 0.f, 0.f};
    float ynr[6], k1r[6], k2r[6];
    unsigned rnd = 0;

#pragma unroll 1
    for (int s = 0; s < NSTEP; s++) {
        const float dt  = dts[s];
        const float dt3 = dt * (1.0f / 3.0f);

#pragma unroll 1
        for (int e = 0; e < 4; e++) {
            // ---- layer 1: h_j = tanh(v @ W1[:,j] + b1_j) ----
            float acc = 0.0f;
#pragma unroll
            for (int k = 0; k < 6; k++) {
                float4 a = vsm4[k * 32 + lane];
                acc = fmaf(a.x, w1r[k].x, acc);
                acc = fmaf(a.y, w1r[k].y, acc);
                acc = fmaf(a.z, w1r[k].z, acc);
                acc = fmaf(a.w, w1r[k].w, acc);
            }
            acc = warp_sum(acc);
            unsigned th = ++rnd;
            if (lane == 0) pub8(&g_x[th & 1][bid][warp], tanhf(acc + b1c), th);
            __syncthreads();   // ALL publishes issued before ANY lane spins
            if (tid < G) {
                float hv[6];
                wait_packet(g_x[th & 1][tid], th, hv);
                float* d = hsm + tid * 6;
#pragma unroll
                for (int q = 0; q < 6; q++) d[q] = hv[q];
            }
            __syncthreads();

            // ---- layer 2: k_j = h @ W2[:,j] + b2_j ----
            float acc2 = 0.0f;
#pragma unroll
            for (int k = 0; k < 6; k++) {
                float4 a = hsm4[k * 32 + lane];
                acc2 = fmaf(a.x, w2r[k].x, acc2);
                acc2 = fmaf(a.y, w2r[k].y, acc2);
                acc2 = fmaf(a.z, w2r[k].z, acc2);
                acc2 = fmaf(a.w, w2r[k].w, acc2);
            }
            acc2 = warp_sum(acc2);
            unsigned tk = ++rnd;
            if (lane == 0) pub8(&g_x[tk & 1][bid][warp], acc2 + b2c, tk);
            __syncthreads();   // publish-before-poll
            if (tid < G) {
                float kv[6];
                wait_packet(g_x[tk & 1][tid], tk, kv);
                float* v = vsm + tid * 6;
                if (e == 0) {
#pragma unroll
                    for (int q = 0; q < 6; q++) {
                        k1r[q] = kv[q];
                        ynr[q] = fmaf(dt * 0.125f, kv[q], yr[q]);
                        v[q]   = fmaf(dt3, kv[q], yr[q]);
                    }
                } else if (e == 1) {
#pragma unroll
                    for (int q = 0; q < 6; q++) {
                        k2r[q] = kv[q];
                        ynr[q] = fmaf(dt * 0.375f, kv[q], ynr[q]);
                        v[q]   = yr[q] + dt * kv[q] - dt3 * k1r[q];
                    }
                } else if (e == 2) {
#pragma unroll
                    for (int q = 0; q < 6; q++) {
                        ynr[q] = fmaf(dt * 0.375f, kv[q], ynr[q]);
                        v[q]   = yr[q] + dt * (k1r[q] - k2r[q] + kv[q]);
                    }
                } else {
#pragma unroll
                    for (int q = 0; q < 6; q++) {
                        yr[q] = fmaf(dt * 0.125f, kv[q], ynr[q]);
                        v[q]  = yr[q];
                    }
                }
            }
            __syncthreads();
        }
    }
    // vsm now holds yT (not modified below).

    // ---- regressor 768->128->256->128->6 via tagged 8B rounds ----
    {
        float o1 = block_dot(vsm, 768, rw1, 128, bid, rb1, red);
        unsigned tr = ++rnd; uint2* b = g_s[tr & 1];
        if (tid == 0) pub8(&b[bid], lrelu(o1), tr);
        __syncthreads();
        if (tid < 128) hsm[tid] = wait8(&b[tid], tr);
        __syncthreads();

        float o2a = block_dot(hsm, 128, rw2, 256, bid,       rb2, red);
        float o2b = block_dot(hsm, 128, rw2, 256, bid + 128, rb2, red);
        tr = ++rnd; b = g_s[tr & 1];
        if (tid == 0) {
            pub8(&b[bid],       lrelu(o2a), tr);
            pub8(&b[bid + 128], lrelu(o2b), tr);
        }
        __syncthreads();
        for (int i = tid; i < 256; i += T) hsm[i] = wait8(&b[i], tr);
        __syncthreads();

        float o3 = block_dot(hsm, 256, rw3, 128, bid, rb3, red);
        tr = ++rnd; b = g_s[tr & 1];
        if (tid == 0) pub8(&b[bid], lrelu(o3), tr);
        __syncthreads();                     // hsm reads done; publish ordered
        if (tid < 128) hsm[tid] = wait8(&b[tid], tr);
        __syncthreads();

        float o4 = block_dot(hsm, 128, rw4, 6, bid % 6, rb4, red);
        tr = ++rnd; b = g_s[tr & 1];
        if (tid == 0 && bid < 6) pub8(&b[bid], o4, tr);   // no activation
        __syncthreads();
        if (tid < 6) pose_s[tid] = wait8(&b[tid], tr);
        __syncthreads();
    }

    // ---- outputs: [pose (256*6) | yT (256*768)] ----
    for (int idx = bid * T + tid; idx < out_n; idx += G * T) {
        out[idx] = (idx < 1536) ? pose_s[idx % 6] : vsm[(idx - 1536) % 768];
    }
}

extern "C" void kernel_launch(void* const* d_in, const int* in_sizes, int n_in,
                              void* d_out, int out_size) {
    // order: fv, fv_alter, fi, dec (unused), ts, ode_w1, ode_b1, ode_w2, ode_b2,
    // reg_w1, reg_b1, reg_w2, reg_b2, reg_w3, reg_b3, reg_w4, reg_b4
    const float* ts  = (const float*)d_in[4];
    const float* w1  = (const float*)d_in[5];
    const float* b1  = (const float*)d_in[6];
    const float* w2  = (const float*)d_in[7];
    const float* b2  = (const float*)d_in[8];
    const float* rw1 = (const float*)d_in[9];
    const float* rb1 = (const float*)d_in[10];
    const float* rw2 = (const float*)d_in[11];
    const float* rb2 = (const float*)d_in[12];
    const float* rw3 = (const float*)d_in[13];
    const float* rb3 = (const float*)d_in[14];
    const float* rw4 = (const float*)d_in[15];
    const float* rb4 = (const float*)d_in[16];

    pose_ode_kernel<<<G, T>>>(ts, w1, b1, w2, b2,
                              rw1, rb1, rw2, rb2, rw3, rb3, rw4, rb4,
                              (float*)d_out, out_size);
}

// round 8
// speedup vs baseline: 2.8956x; 1.8998x over previous
#include <cuda_runtime.h>

// PoseODE: y' = MLP(y), y0 = 0, batch-invariant -> single 768-vector trajectory.
// 512 sequential matvec stages across 64 CTAs (12 columns each). Cross-CTA
// exchange: SINGLE-WRITER 64B packet per CTA per round, four self-validating
// 16B chunks {tag,v,v,v} (each STG.128 single-copy atomic). R5-proven
// transport: single writer => consumers succeed on ~first poll, no L2 storm.
// Monotonic tags -> no init, no grid barrier, replay-safe.

#define F      768
#define G      64    // CTAs
#define W      12    // warps per CTA; warp w owns column bid*12 + w
#define T      384
#define NSTEP  64

// packet row = 4 x uint4 = 64B: chunk c = {tag, v(3c), v(3c+1), v(3c+2)}
__device__ __align__(128) uint4 g_x[2][G][4] = {};
__device__ __align__(128) uint2 g_s[2][256]  = {};   // regressor rounds

static __device__ __forceinline__ uint4 ldcg_v4(const void* p) {
    uint4 r;
    asm volatile("ld.global.cg.v4.u32 {%0,%1,%2,%3},[%4];"
                 : "=r"(r.x), "=r"(r.y), "=r"(r.z), "=r"(r.w) : "l"(p));
    return r;
}
static __device__ __forceinline__ void stcg_v4(uint4* p, unsigned a, unsigned b,
                                               unsigned c, unsigned d) {
    asm volatile("st.global.cg.v4.u32 [%0],{%1,%2,%3,%4};"
                 :: "l"(p), "r"(a), "r"(b), "r"(c), "r"(d) : "memory");
}
static __device__ __forceinline__ void pub8(uint2* s, float v, unsigned tag) {
    asm volatile("st.global.cg.v2.u32 [%0],{%1,%2};"
                 :: "l"(s), "r"(__float_as_uint(v)), "r"(tag) : "memory");
}
static __device__ __forceinline__ float wait8(const uint2* s, unsigned tag) {
    unsigned v, t;
    do {
        asm volatile("ld.global.cg.v2.u32 {%0,%1},[%2];" : "=r"(v), "=r"(t) : "l"(s));
    } while (t != tag);
    return __uint_as_float(v);
}

// Poll one CTA's 64B packet until all 4 chunk tags match; return 12 values.
static __device__ __forceinline__ void wait_packet(const uint4* p, unsigned tag, float* o) {
    uint4 a, b, c, d;
    do {
        a = ldcg_v4(p);
        b = ldcg_v4(p + 1);
        c = ldcg_v4(p + 2);
        d = ldcg_v4(p + 3);
    } while ((a.x ^ tag) | (b.x ^ tag) | (c.x ^ tag) | (d.x ^ tag));
    o[0]=__uint_as_float(a.y); o[1] =__uint_as_float(a.z); o[2] =__uint_as_float(a.w);
    o[3]=__uint_as_float(b.y); o[4] =__uint_as_float(b.z); o[5] =__uint_as_float(b.w);
    o[6]=__uint_as_float(c.y); o[7] =__uint_as_float(c.z); o[8] =__uint_as_float(c.w);
    o[9]=__uint_as_float(d.y); o[10]=__uint_as_float(d.z); o[11]=__uint_as_float(d.w);
}

static __device__ __forceinline__ float lrelu(float x) { return x > 0.0f ? x : 0.1f * x; }

static __device__ __forceinline__ float warp_sum(float a) {
#pragma unroll
    for (int o = 16; o; o >>= 1) a += __shfl_xor_sync(0xffffffffu, a, o);
    return a;
}

// Block-wide dot of SMEM vector src[0..L) with column `col` of wmat[L][outF].
__device__ __forceinline__ float block_dot(const float* src, int L,
                                           const float* wmat, int outF, int col,
                                           const float* bias, volatile float* red) {
    int tid = threadIdx.x, warp = tid >> 5, lane = tid & 31;
    float p = 0.0f;
    for (int i = tid; i < L; i += T) p = fmaf(src[i], __ldg(&wmat[i * outF + col]), p);
    p = warp_sum(p);
    if (lane == 0) red[warp] = p;
    __syncthreads();
    float s = 0.0f;
    if (tid == 0) {
        for (int w = 0; w < W; w++) s += red[w];
        s += __ldg(&bias[col]);
    }
    __syncthreads();
    return s;
}

// tid0: read 12 packed values from pack4, publish as 4 self-validating chunks.
static __device__ __forceinline__ void publish12(const float4* pack4, unsigned tag,
                                                 uint4* base) {
    float4 p0 = pack4[0], p1 = pack4[1], p2 = pack4[2];
    stcg_v4(base+0, tag, __float_as_uint(p0.x), __float_as_uint(p0.y), __float_as_uint(p0.z));
    stcg_v4(base+1, tag, __float_as_uint(p0.w), __float_as_uint(p1.x), __float_as_uint(p1.y));
    stcg_v4(base+2, tag, __float_as_uint(p1.z), __float_as_uint(p1.w), __float_as_uint(p2.x));
    stcg_v4(base+3, tag, __float_as_uint(p2.y), __float_as_uint(p2.z), __float_as_uint(p2.w));
}

__global__ __launch_bounds__(T, 1) void pose_ode_kernel(
    const float* __restrict__ ts,
    const float* __restrict__ w1, const float* __restrict__ b1,
    const float* __restrict__ w2, const float* __restrict__ b2,
    const float* __restrict__ rw1, const float* __restrict__ rb1,
    const float* __restrict__ rw2, const float* __restrict__ rb2,
    const float* __restrict__ rw3, const float* __restrict__ rb3,
    const float* __restrict__ rw4, const float* __restrict__ rb4,
    float* __restrict__ out, int out_n)
{
    __shared__ float  wstage[W * F];     // 36 KB one-time staging; regressor scratch after
    __shared__ float4 vsm4[F / 4];       // stage input vector / final yT
    __shared__ float4 hsm4[F / 4];       // hidden vector / regressor scratch
    __shared__ float4 pack4[3];          // 12 packed outputs
    __shared__ float  red[16];
    __shared__ float  pose_s[8];
    __shared__ float  dts[NSTEP];

    float* vsm = (float*)vsm4;
    float* hsm = (float*)hsm4;
    float* pack_s = (float*)pack4;

    const int tid  = threadIdx.x;
    const int warp = tid >> 5;
    const int lane = tid & 31;
    const int bid  = blockIdx.x;
    const int c0   = bid * W;
    const int j    = c0 + warp;          // this warp's output column

    if (tid < NSTEP) dts[tid] = __ldg(&ts[tid + 1]) - __ldg(&ts[tid]);

    // ---- stage weight columns into SMEM (coalesced), then into registers ----
    float4 w1r[6], w2r[6];
    for (int idx = tid; idx < W * F; idx += T) {
        int i = idx / W, r = idx - i * W;
        wstage[r * F + i] = w1[i * F + c0 + r];
    }
    __syncthreads();
#pragma unroll
    for (int k = 0; k < 6; k++)
        w1r[k] = ((const float4*)(wstage + warp * F))[k * 32 + lane];
    __syncthreads();
    for (int idx = tid; idx < W * F; idx += T) {
        int i = idx / W, r = idx - i * W;
        wstage[r * F + i] = w2[i * F + c0 + r];
    }
    __syncthreads();
#pragma unroll
    for (int k = 0; k < 6; k++)
        w2r[k] = ((const float4*)(wstage + warp * F))[k * 32 + lane];

    const float b1c = __ldg(&b1[j]);
    const float b2c = __ldg(&b2[j]);

    // ---- initial state: y0 = 0 ----
    if (tid < F / 4) vsm4[tid] = make_float4(0.f, 0.f, 0.f, 0.f);
    __syncthreads();

    // Poller thread t (<64) owns state elements [12t, 12t+12) == its packet.
    float yr[12], ynr[12], k1r[12], k2r[12];
#pragma unroll
    for (int q = 0; q < 12; q++) yr[q] = 0.f;
    unsigned rnd = 0;

#pragma unroll 1
    for (int s = 0; s < NSTEP; s++) {
        const float dt  = dts[s];
        const float dt3 = dt * (1.0f / 3.0f);

#pragma unroll 1
        for (int e = 0; e < 4; e++) {
            // ---- layer 1: h_j = tanh(v @ W1[:,j] + b1_j) ----
            float a0 = 0.f, a1 = 0.f, a2 = 0.f, a3 = 0.f;
#pragma unroll
            for (int k = 0; k < 6; k++) {
                float4 a = vsm4[k * 32 + lane];
                a0 = fmaf(a.x, w1r[k].x, a0);
                a1 = fmaf(a.y, w1r[k].y, a1);
                a2 = fmaf(a.z, w1r[k].z, a2);
                a3 = fmaf(a.w, w1r[k].w, a3);
            }
            float acc = warp_sum((a0 + a1) + (a2 + a3));
            if (lane == 0) pack_s[warp] = tanhf(acc + b1c);
            __syncthreads();                    // pack_s complete
            unsigned th = ++rnd;
            if (tid == 0) publish12(pack4, th, g_x[th & 1][bid]);
            if (tid < G) {
                float hv[12];
                wait_packet(g_x[th & 1][tid], th, hv);
                float4* d = (float4*)(hsm + tid * 12);
                d[0] = make_float4(hv[0], hv[1], hv[2],  hv[3]);
                d[1] = make_float4(hv[4], hv[5], hv[6],  hv[7]);
                d[2] = make_float4(hv[8], hv[9], hv[10], hv[11]);
            }
            __syncthreads();                    // hsm complete

            // ---- layer 2: k_j = h @ W2[:,j] + b2_j ----
            float c0a = 0.f, c1a = 0.f, c2a = 0.f, c3a = 0.f;
#pragma unroll
            for (int k = 0; k < 6; k++) {
                float4 a = hsm4[k * 32 + lane];
                c0a = fmaf(a.x, w2r[k].x, c0a);
                c1a = fmaf(a.y, w2r[k].y, c1a);
                c2a = fmaf(a.z, w2r[k].z, c2a);
                c3a = fmaf(a.w, w2r[k].w, c3a);
            }
            float acc2 = warp_sum((c0a + c1a) + (c2a + c3a));
            if (lane == 0) pack_s[warp] = acc2 + b2c;
            __syncthreads();                    // pack_s complete
            unsigned tk = ++rnd;
            if (tid == 0) publish12(pack4, tk, g_x[tk & 1][bid]);
            if (tid < G) {
                float kv[12], vv[12];
                wait_packet(g_x[tk & 1][tid], tk, kv);
                if (e == 0) {
#pragma unroll
                    for (int q = 0; q < 12; q++) {
                        k1r[q] = kv[q];
                        ynr[q] = fmaf(dt * 0.125f, kv[q], yr[q]);
                        vv[q]  = fmaf(dt3, kv[q], yr[q]);
                    }
                } else if (e == 1) {
#pragma unroll
                    for (int q = 0; q < 12; q++) {
                        k2r[q] = kv[q];
                        ynr[q] = fmaf(dt * 0.375f, kv[q], ynr[q]);
                        vv[q]  = yr[q] + dt * kv[q] - dt3 * k1r[q];
                    }
                } else if (e == 2) {
#pragma unroll
                    for (int q = 0; q < 12; q++) {
                        ynr[q] = fmaf(dt * 0.375f, kv[q], ynr[q]);
                        vv[q]  = yr[q] + dt * (k1r[q] - k2r[q] + kv[q]);
                    }
                } else {
#pragma unroll
                    for (int q = 0; q < 12; q++) {
                        yr[q] = fmaf(dt * 0.125f, kv[q], ynr[q]);
                        vv[q] = yr[q];
                    }
                }
                float4* v = (float4*)(vsm + tid * 12);
                v[0] = make_float4(vv[0], vv[1], vv[2],  vv[3]);
                v[1] = make_float4(vv[4], vv[5], vv[6],  vv[7]);
                v[2] = make_float4(vv[8], vv[9], vv[10], vv[11]);
            }
            __syncthreads();                    // vsm complete
        }
    }
    // vsm now holds yT (not modified below).

    // ---- regressor 768->128->256->128->6 via tagged 8B rounds ----
    float* scratch = wstage;   // weight staging no longer needed
    {
        float o1a = block_dot(vsm, 768, rw1, 128, bid,      rb1, red);
        float o1b = block_dot(vsm, 768, rw1, 128, bid + 64, rb1, red);
        unsigned tr = ++rnd; uint2* b = g_s[tr & 1];
        if (tid == 0) {
            pub8(&b[bid],      lrelu(o1a), tr);
            pub8(&b[bid + 64], lrelu(o1b), tr);
        }
        if (tid < 128) hsm[tid] = wait8(&b[tid], tr);
        __syncthreads();

        float o2[4];
#pragma unroll
        for (int m = 0; m < 4; m++)
            o2[m] = block_dot(hsm, 128, rw2, 256, bid + m * 64, rb2, red);
        tr = ++rnd; b = g_s[tr & 1];
        if (tid == 0)
#pragma unroll
            for (int m = 0; m < 4; m++) pub8(&b[bid + m * 64], lrelu(o2[m]), tr);
        for (int i = tid; i < 256; i += T) scratch[i] = wait8(&b[i], tr);
        __syncthreads();

        float o3a = block_dot(scratch, 256, rw3, 128, bid,      rb3, red);
        float o3b = block_dot(scratch, 256, rw3, 128, bid + 64, rb3, red);
        tr = ++rnd; b = g_s[tr & 1];
        if (tid == 0) {
            pub8(&b[bid],      lrelu(o3a), tr);
            pub8(&b[bid + 64], lrelu(o3b), tr);
        }
        __syncthreads();                 // hsm reads done above
        if (tid < 128) hsm[tid] = wait8(&b[tid], tr);
        __syncthreads();

        float o4 = block_dot(hsm, 128, rw4, 6, bid % 6, rb4, red);
        tr = ++rnd; b = g_s[tr & 1];
        if (tid == 0 && bid < 6) pub8(&b[bid], o4, tr);   // no activation
        if (tid < 6) pose_s[tid] = wait8(&b[tid], tr);
        __syncthreads();
    }

    // ---- outputs: [pose (256*6) | yT (256*768)] ----
    for (int idx = bid * T + tid; idx < out_n; idx += G * T) {
        out[idx] = (idx < 1536) ? pose_s[idx % 6] : vsm[(idx - 1536) % 768];
    }
}

extern "C" void kernel_launch(void* const* d_in, const int* in_sizes, int n_in,
                              void* d_out, int out_size) {
    // order: fv, fv_alter, fi, dec (unused), ts, ode_w1, ode_b1, ode_w2, ode_b2,
    // reg_w1, reg_b1, reg_w2, reg_b2, reg_w3, reg_b3, reg_w4, reg_b4
    const float* ts  = (const float*)d_in[4];
    const float* w1  = (const float*)d_in[5];
    const float* b1  = (const float*)d_in[6];
    const float* w2  = (const float*)d_in[7];
    const float* b2  = (const float*)d_in[8];
    const float* rw1 = (const float*)d_in[9];
    const float* rb1 = (const float*)d_in[10];
    const float* rw2 = (const float*)d_in[11];
    const float* rb2 = (const float*)d_in[12];
    const float* rw3 = (const float*)d_in[13];
    const float* rb3 = (const float*)d_in[14];
    const float* rw4 = (const float*)d_in[15];
    const float* rb4 = (const float*)d_in[16];

    pose_ode_kernel<<<G, T>>>(ts, w1, b1, w2, b2,
                              rw1, rb1, rw2, rb2, rw3, rb3, rw4, rb4,
                              (float*)d_out, out_size);
}

// round 9
// speedup vs baseline: 3.2298x; 1.1154x over previous
#include <cuda_runtime.h>

// PoseODE: y' = MLP(y), y0 = 0, batch-invariant -> single 768-vector trajectory.
// 512 sequential matvec stages across 64 CTAs (12 columns each). Cross-CTA
// exchange: SINGLE-WRITER 64B packet per CTA per round, four self-validating
// 16B chunks {tag,v,v,v} (each STG.128 single-copy atomic). R9: 6 warps x
// 2 columns per warp -> vector read once per warp (halves dot SMEM traffic),
// smaller pre-publish skew pool. Monotonic tags -> no init, replay-safe.

#define F      768
#define G      64    // CTAs
#define NC     12    // columns per CTA
#define WP     6     // warps per CTA; warp w owns columns bid*12 + 2w, 2w+1
#define T      192
#define NSTEP  64

// packet row = 4 x uint4 = 64B: chunk c = {tag, v(3c), v(3c+1), v(3c+2)}
__device__ __align__(128) uint4 g_x[2][G][4] = {};
__device__ __align__(128) uint2 g_s[2][256]  = {};   // regressor rounds

static __device__ __forceinline__ uint4 ldcg_v4(const void* p) {
    uint4 r;
    asm volatile("ld.global.cg.v4.u32 {%0,%1,%2,%3},[%4];"
                 : "=r"(r.x), "=r"(r.y), "=r"(r.z), "=r"(r.w) : "l"(p));
    return r;
}
static __device__ __forceinline__ void stcg_v4(uint4* p, unsigned a, unsigned b,
                                               unsigned c, unsigned d) {
    asm volatile("st.global.cg.v4.u32 [%0],{%1,%2,%3,%4};"
                 :: "l"(p), "r"(a), "r"(b), "r"(c), "r"(d) : "memory");
}
static __device__ __forceinline__ void pub8(uint2* s, float v, unsigned tag) {
    asm volatile("st.global.cg.v2.u32 [%0],{%1,%2};"
                 :: "l"(s), "r"(__float_as_uint(v)), "r"(tag) : "memory");
}
static __device__ __forceinline__ float wait8(const uint2* s, unsigned tag) {
    unsigned v, t;
    do {
        asm volatile("ld.global.cg.v2.u32 {%0,%1},[%2];" : "=r"(v), "=r"(t) : "l"(s));
    } while (t != tag);
    return __uint_as_float(v);
}

// Poll one CTA's 64B packet until all 4 chunk tags match; return 12 values.
static __device__ __forceinline__ void wait_packet(const uint4* p, unsigned tag, float* o) {
    uint4 a, b, c, d;
    do {
        a = ldcg_v4(p);
        b = ldcg_v4(p + 1);
        c = ldcg_v4(p + 2);
        d = ldcg_v4(p + 3);
    } while ((a.x ^ tag) | (b.x ^ tag) | (c.x ^ tag) | (d.x ^ tag));
    o[0]=__uint_as_float(a.y); o[1] =__uint_as_float(a.z); o[2] =__uint_as_float(a.w);
    o[3]=__uint_as_float(b.y); o[4] =__uint_as_float(b.z); o[5] =__uint_as_float(b.w);
    o[6]=__uint_as_float(c.y); o[7] =__uint_as_float(c.z); o[8] =__uint_as_float(c.w);
    o[9]=__uint_as_float(d.y); o[10]=__uint_as_float(d.z); o[11]=__uint_as_float(d.w);
}

static __device__ __forceinline__ float lrelu(float x) { return x > 0.0f ? x : 0.1f * x; }

static __device__ __forceinline__ float warp_sum(float a) {
#pragma unroll
    for (int o = 16; o; o >>= 1) a += __shfl_xor_sync(0xffffffffu, a, o);
    return a;
}

// Dot of the SMEM vector with TWO weight columns (both in registers).
// Returns both sums on every lane (butterfly-reduced).
static __device__ __forceinline__ void dot2(const float4* __restrict__ src4,
                                            const float4* wa, const float4* wb,
                                            int lane, float& ra, float& rb) {
    float a0=0.f, a1=0.f, b0=0.f, b1=0.f;
#pragma unroll
    for (int k = 0; k < 6; k += 2) {
        float4 v0 = src4[k * 32 + lane];
        float4 v1 = src4[(k + 1) * 32 + lane];
        a0 = fmaf(v0.x, wa[k].x, a0);   b0 = fmaf(v0.x, wb[k].x, b0);
        a0 = fmaf(v0.y, wa[k].y, a0);   b0 = fmaf(v0.y, wb[k].y, b0);
        a0 = fmaf(v0.z, wa[k].z, a0);   b0 = fmaf(v0.z, wb[k].z, b0);
        a0 = fmaf(v0.w, wa[k].w, a0);   b0 = fmaf(v0.w, wb[k].w, b0);
        a1 = fmaf(v1.x, wa[k+1].x, a1); b1 = fmaf(v1.x, wb[k+1].x, b1);
        a1 = fmaf(v1.y, wa[k+1].y, a1); b1 = fmaf(v1.y, wb[k+1].y, b1);
        a1 = fmaf(v1.z, wa[k+1].z, a1); b1 = fmaf(v1.z, wb[k+1].z, b1);
        a1 = fmaf(v1.w, wa[k+1].w, a1); b1 = fmaf(v1.w, wb[k+1].w, b1);
    }
    float a = a0 + a1, b = b0 + b1;
#pragma unroll
    for (int o = 16; o; o >>= 1) {
        a += __shfl_xor_sync(0xffffffffu, a, o);
        b += __shfl_xor_sync(0xffffffffu, b, o);
    }
    ra = a; rb = b;
}

// Block-wide dot of SMEM vector src[0..L) with column `col` of wmat[L][outF].
__device__ __forceinline__ float block_dot(const float* src, int L,
                                           const float* wmat, int outF, int col,
                                           const float* bias, volatile float* red) {
    int tid = threadIdx.x, warp = tid >> 5, lane = tid & 31;
    float p = 0.0f;
    for (int i = tid; i < L; i += T) p = fmaf(src[i], __ldg(&wmat[i * outF + col]), p);
    p = warp_sum(p);
    if (lane == 0) red[warp] = p;
    __syncthreads();
    float s = 0.0f;
    if (tid == 0) {
        for (int w = 0; w < WP; w++) s += red[w];
        s += __ldg(&bias[col]);
    }
    __syncthreads();
    return s;
}

// tid0: read 12 packed values from pack4, publish as 4 self-validating chunks.
static __device__ __forceinline__ void publish12(const float4* pack4, unsigned tag,
                                                 uint4* base) {
    float4 p0 = pack4[0], p1 = pack4[1], p2 = pack4[2];
    stcg_v4(base+0, tag, __float_as_uint(p0.x), __float_as_uint(p0.y), __float_as_uint(p0.z));
    stcg_v4(base+1, tag, __float_as_uint(p0.w), __float_as_uint(p1.x), __float_as_uint(p1.y));
    stcg_v4(base+2, tag, __float_as_uint(p1.z), __float_as_uint(p1.w), __float_as_uint(p2.x));
    stcg_v4(base+3, tag, __float_as_uint(p2.y), __float_as_uint(p2.z), __float_as_uint(p2.w));
}

__global__ __launch_bounds__(T, 1) void pose_ode_kernel(
    const float* __restrict__ ts,
    const float* __restrict__ w1, const float* __restrict__ b1,
    const float* __restrict__ w2, const float* __restrict__ b2,
    const float* __restrict__ rw1, const float* __restrict__ rb1,
    const float* __restrict__ rw2, const float* __restrict__ rb2,
    const float* __restrict__ rw3, const float* __restrict__ rb3,
    const float* __restrict__ rw4, const float* __restrict__ rb4,
    float* __restrict__ out, int out_n)
{
    __shared__ float  wstage[NC * F];    // 36 KB one-time staging; regressor scratch
    __shared__ float4 vsm4[F / 4];       // stage input vector / final yT
    __shared__ float4 hsm4[F / 4];       // hidden vector / regressor scratch
    __shared__ float4 pack4[3];          // 12 packed outputs
    __shared__ float  red[8];
    __shared__ float  pose_s[8];
    __shared__ float  dts[NSTEP];

    float* vsm = (float*)vsm4;
    float* hsm = (float*)hsm4;
    float* pack_s = (float*)pack4;

    const int tid  = threadIdx.x;
    const int warp = tid >> 5;
    const int lane = tid & 31;
    const int half = (lane >> 4) & 1;    // lane0 -> col 2w, lane16 -> col 2w+1
    const int bid  = blockIdx.x;
    const int c0   = bid * NC;

    if (tid < NSTEP) dts[tid] = __ldg(&ts[tid + 1]) - __ldg(&ts[tid]);

    // ---- stage weight columns into SMEM (coalesced), then into registers ----
    float4 w1a[6], w1b[6], w2a[6], w2b[6];
    for (int idx = tid; idx < NC * F; idx += T) {
        int i = idx / NC, r = idx - i * NC;
        wstage[r * F + i] = w1[i * F + c0 + r];
    }
    __syncthreads();
#pragma unroll
    for (int k = 0; k < 6; k++) {
        w1a[k] = ((const float4*)(wstage + (2 * warp)     * F))[k * 32 + lane];
        w1b[k] = ((const float4*)(wstage + (2 * warp + 1) * F))[k * 32 + lane];
    }
    __syncthreads();
    for (int idx = tid; idx < NC * F; idx += T) {
        int i = idx / NC, r = idx - i * NC;
        wstage[r * F + i] = w2[i * F + c0 + r];
    }
    __syncthreads();
#pragma unroll
    for (int k = 0; k < 6; k++) {
        w2a[k] = ((const float4*)(wstage + (2 * warp)     * F))[k * 32 + lane];
        w2b[k] = ((const float4*)(wstage + (2 * warp + 1) * F))[k * 32 + lane];
    }

    // per-lane bias for this lane's writer column (lane0: 2w, lane16: 2w+1)
    const float b1c = __ldg(&b1[c0 + 2 * warp + half]);
    const float b2c = __ldg(&b2[c0 + 2 * warp + half]);

    // ---- initial state: y0 = 0 ----
    if (tid < F / 4) vsm4[tid] = make_float4(0.f, 0.f, 0.f, 0.f);
    __syncthreads();

    // Poller thread t (<64) owns state elements [12t, 12t+12) == its packet.
    float yr[12], ynr[12], k1r[12], k2r[12];
#pragma unroll
    for (int q = 0; q < 12; q++) yr[q] = 0.f;
    unsigned rnd = 0;

#pragma unroll 1
    for (int s = 0; s < NSTEP; s++) {
        const float dt  = dts[s];
        const float dt3 = dt * (1.0f / 3.0f);

#pragma unroll 1
        for (int e = 0; e < 4; e++) {
            // ---- layer 1: h = tanh(v @ W1 + b1), 2 columns per warp ----
            float accA, accB;
            dot2(vsm4, w1a, w1b, lane, accA, accB);
            float hvv = tanhf((half ? accB : accA) + b1c);
            if (lane == 0 || lane == 16) pack_s[2 * warp + half] = hvv;
            __syncthreads();                    // pack_s complete
            unsigned th = ++rnd;
            if (tid == 0) publish12(pack4, th, g_x[th & 1][bid]);
            if (tid < G) {
                float hv[12];
                wait_packet(g_x[th & 1][tid], th, hv);
                float4* d = (float4*)(hsm + tid * 12);
                d[0] = make_float4(hv[0], hv[1], hv[2],  hv[3]);
                d[1] = make_float4(hv[4], hv[5], hv[6],  hv[7]);
                d[2] = make_float4(hv[8], hv[9], hv[10], hv[11]);
            }
            __syncthreads();                    // hsm complete

            // ---- layer 2: k = h @ W2 + b2 ----
            dot2(hsm4, w2a, w2b, lane, accA, accB);
            float kvv = (half ? accB : accA) + b2c;
            if (lane == 0 || lane == 16) pack_s[2 * warp + half] = kvv;
            __syncthreads();                    // pack_s complete
            unsigned tk = ++rnd;
            if (tid == 0) publish12(pack4, tk, g_x[tk & 1][bid]);
            if (tid < G) {
                float kv[12], vv[12];
                wait_packet(g_x[tk & 1][tid], tk, kv);
                if (e == 0) {
#pragma unroll
                    for (int q = 0; q < 12; q++) {
                        k1r[q] = kv[q];
                        ynr[q] = fmaf(dt * 0.125f, kv[q], yr[q]);
                        vv[q]  = fmaf(dt3, kv[q], yr[q]);
                    }
                } else if (e == 1) {
#pragma unroll
                    for (int q = 0; q < 12; q++) {
                        k2r[q] = kv[q];
                        ynr[q] = fmaf(dt * 0.375f, kv[q], ynr[q]);
                        vv[q]  = yr[q] + dt * kv[q] - dt3 * k1r[q];
                    }
                } else if (e == 2) {
#pragma unroll
                    for (int q = 0; q < 12; q++) {
                        ynr[q] = fmaf(dt * 0.375f, kv[q], ynr[q]);
                        vv[q]  = yr[q] + dt * (k1r[q] - k2r[q] + kv[q]);
                    }
                } else {
#pragma unroll
                    for (int q = 0; q < 12; q++) {
                        yr[q] = fmaf(dt * 0.125f, kv[q], ynr[q]);
                        vv[q] = yr[q];
                    }
                }
                float4* v = (float4*)(vsm + tid * 12);
                v[0] = make_float4(vv[0], vv[1], vv[2],  vv[3]);
                v[1] = make_float4(vv[4], vv[5], vv[6],  vv[7]);
                v[2] = make_float4(vv[8], vv[9], vv[10], vv[11]);
            }
            __syncthreads();                    // vsm complete
        }
    }
    // vsm now holds yT (not modified below).

    // ---- regressor 768->128->256->128->6 via tagged 8B rounds ----
    float* scratch = wstage;   // weight staging no longer needed
    {
        float o1a = block_dot(vsm, 768, rw1, 128, bid,      rb1, red);
        float o1b = block_dot(vsm, 768, rw1, 128, bid + 64, rb1, red);
        unsigned tr = ++rnd; uint2* b = g_s[tr & 1];
        if (tid == 0) {
            pub8(&b[bid],      lrelu(o1a), tr);
            pub8(&b[bid + 64], lrelu(o1b), tr);
        }
        if (tid < 128) hsm[tid] = wait8(&b[tid], tr);
        __syncthreads();

        float o2[4];
#pragma unroll
        for (int m = 0; m < 4; m++)
            o2[m] = block_dot(hsm, 128, rw2, 256, bid + m * 64, rb2, red);
        tr = ++rnd; b = g_s[tr & 1];
        if (tid == 0)
#pragma unroll
            for (int m = 0; m < 4; m++) pub8(&b[bid + m * 64], lrelu(o2[m]), tr);
        for (int i = tid; i < 256; i += T) scratch[i] = wait8(&b[i], tr);
        __syncthreads();

        float o3a = block_dot(scratch, 256, rw3, 128, bid,      rb3, red);
        float o3b = block_dot(scratch, 256, rw3, 128, bid + 64, rb3, red);
        tr = ++rnd; b = g_s[tr & 1];
        if (tid == 0) {
            pub8(&b[bid],      lrelu(o3a), tr);
            pub8(&b[bid + 64], lrelu(o3b), tr);
        }
        __syncthreads();                 // hsm reads done above
        if (tid < 128) hsm[tid] = wait8(&b[tid], tr);
        __syncthreads();

        float o4 = block_dot(hsm, 128, rw4, 6, bid % 6, rb4, red);
        tr = ++rnd; b = g_s[tr & 1];
        if (tid == 0 && bid < 6) pub8(&b[bid], o4, tr);   // no activation
        if (tid < 6) pose_s[tid] = wait8(&b[tid], tr);
        __syncthreads();
    }

    // ---- outputs: [pose (256*6) | yT (256*768)] ----
    for (int idx = bid * T + tid; idx < out_n; idx += G * T) {
        out[idx] = (idx < 1536) ? pose_s[idx % 6] : vsm[(idx - 1536) % 768];
    }
}

extern "C" void kernel_launch(void* const* d_in, const int* in_sizes, int n_in,
                              void* d_out, int out_size) {
    // order: fv, fv_alter, fi, dec (unused), ts, ode_w1, ode_b1, ode_w2, ode_b2,
    // reg_w1, reg_b1, reg_w2, reg_b2, reg_w3, reg_b3, reg_w4, reg_b4
    const float* ts  = (const float*)d_in[4];
    const float* w1  = (const float*)d_in[5];
    const float* b1  = (const float*)d_in[6];
    const float* w2  = (const float*)d_in[7];
    const float* b2  = (const float*)d_in[8];
    const float* rw1 = (const float*)d_in[9];
    const float* rb1 = (const float*)d_in[10];
    const float* rw2 = (const float*)d_in[11];
    const float* rb2 = (const float*)d_in[12];
    const float* rw3 = (const float*)d_in[13];
    const float* rb3 = (const float*)d_in[14];
    const float* rw4 = (const float*)d_in[15];
    const float* rb4 = (const float*)d_in[16];

    pose_ode_kernel<<<G, T>>>(ts, w1, b1, w2, b2,
                              rw1, rb1, rw2, rb2, rw3, rb3, rw4, rb4,
                              (float*)d_out, out_size);
}